// round 1
// baseline (speedup 1.0000x reference)
#include <cuda_runtime.h>

#define BATCH 16
#define HH 128
#define WW 128
#define C4 32   // 128 channels as float4 groups

__device__ __forceinline__ float4 mix4(float4 a, float4 b, float wa, float wb) {
    // wa*a + wb*b
    float4 r;
    r.x = fmaf(wa, a.x, wb * b.x);
    r.y = fmaf(wa, a.y, wb * b.y);
    r.z = fmaf(wa, a.z, wb * b.z);
    r.w = fmaf(wa, a.w, wb * b.w);
    return r;
}

__device__ __forceinline__ float lrelu(float u) {
    // u>=0 -> u ; u<0 -> 0.01u   == max(u, 0.01u)
    return fmaxf(u, 0.01f * u);
}

__device__ __forceinline__ float4 lrelu4(float4 u) {
    float4 r;
    r.x = lrelu(u.x); r.y = lrelu(u.y); r.z = lrelu(u.z); r.w = lrelu(u.w);
    return r;
}

// Each thread: one float4 channel group, 4 consecutive output columns.
// block = (32 c4-lanes, 4 col-groups) = 128 threads
// grid  = (W/(4*4)=8, H=128, B=16)
__global__ __launch_bounds__(128)
void act_filter_kernel(const float4* __restrict__ X, float4* __restrict__ O) {
    const int c4 = threadIdx.x;                         // 0..31
    const int jg = blockIdx.x * blockDim.y + threadIdx.y; // 0..31
    const int j0 = jg * 4;
    const int i  = blockIdx.y;
    const int b  = blockIdx.z;

    const int im = (i > 0) ? i - 1 : 0;
    const int ip = (i < HH - 1) ? i + 1 : HH - 1;

    const size_t rowm = (size_t)(b * HH + im) * WW;
    const size_t row0 = (size_t)(b * HH + i ) * WW;
    const size_t rowp = (size_t)(b * HH + ip) * WW;

    // 6 source columns: j0-1 .. j0+4, clamped to [0, W-1]
    int cols[6];
    cols[0] = (j0 > 0) ? j0 - 1 : 0;
    cols[1] = j0;
    cols[2] = j0 + 1;
    cols[3] = j0 + 2;
    cols[4] = j0 + 3;
    cols[5] = (j0 + 4 < WW) ? j0 + 4 : WW - 1;

    // Vertical interpolations for the two up-rows (p = 2i, q = 2i+1)
    float4 vp[6], vq[6];
#pragma unroll
    for (int t = 0; t < 6; t++) {
        float4 am = X[(rowm + cols[t]) * C4 + c4];
        float4 a0 = X[(row0 + cols[t]) * C4 + c4];
        float4 ap = X[(rowp + cols[t]) * C4 + c4];
        vp[t] = mix4(am, a0, 0.25f, 0.75f);   // 0.25*x[i-1] + 0.75*x[i]
        vq[t] = mix4(ap, a0, 0.25f, 0.75f);   // 0.75*x[i]   + 0.25*x[i+1]
    }

#pragma unroll
    for (int jj = 0; jj < 4; jj++) {
        const int t = jj + 1;
        float4 u00 = mix4(vp[t - 1], vp[t], 0.25f, 0.75f);
        float4 u01 = mix4(vp[t + 1], vp[t], 0.25f, 0.75f);
        float4 u10 = mix4(vq[t - 1], vq[t], 0.25f, 0.75f);
        float4 u11 = mix4(vq[t + 1], vq[t], 0.25f, 0.75f);

        float4 a = lrelu4(u00);
        float4 bq = lrelu4(u01);
        float4 c = lrelu4(u10);
        float4 d = lrelu4(u11);

        float4 s;
        s.x = 0.25f * ((a.x + bq.x) + (c.x + d.x));
        s.y = 0.25f * ((a.y + bq.y) + (c.y + d.y));
        s.z = 0.25f * ((a.z + bq.z) + (c.z + d.z));
        s.w = 0.25f * ((a.w + bq.w) + (c.w + d.w));

        O[(row0 + (j0 + jj)) * C4 + c4] = s;
    }
}

extern "C" void kernel_launch(void* const* d_in, const int* in_sizes, int n_in,
                              void* d_out, int out_size) {
    const float4* X = (const float4*)d_in[0];
    float4* O = (float4*)d_out;
    dim3 block(32, 4, 1);
    dim3 grid(WW / 16, HH, BATCH);  // 8, 128, 16
    act_filter_kernel<<<grid, block>>>(X, O);
}